// round 14
// baseline (speedup 1.0000x reference)
#include <cuda_runtime.h>
#include <cuda_fp16.h>
#include <cstdint>

// ---------------- Problem constants ----------------
#define IN_F   512
#define OUT_F  512
#define NEXP   8
#define NGRP   32
#define TPG    2048
#define NTOK   (NGRP * TPG)
#define CHUNK  32

// ---------------- Scratch (no cudaMalloc allowed) ----------------
__device__ __align__(16) __half g_w[(size_t)NGRP * OUT_F * IN_F];    // 16.7 MB mixed weights fp16
__device__ float g_bias_mix[NGRP * OUT_F];

// ---------------- helpers ----------------
static __device__ __forceinline__ uint32_t smem_u32(const void* p) {
    uint32_t a;
    asm("{ .reg .u64 t; cvta.to.shared.u64 t, %1; cvt.u32.u64 %0, t; }"
        : "=r"(a) : "l"(p));
    return a;
}

static __device__ __forceinline__ void cp_async16_cg(uint32_t dst, const void* src) {
    asm volatile("cp.async.cg.shared.global [%0], [%1], 16;"
                 :: "r"(dst), "l"(src) : "memory");
}
static __device__ __forceinline__ void cp_async_commit() {
    asm volatile("cp.async.commit_group;" ::: "memory");
}

static __device__ __forceinline__ void ldm_x4(uint32_t* r, uint32_t addr) {
    asm volatile("ldmatrix.sync.aligned.m8n8.x4.shared.b16 {%0,%1,%2,%3}, [%4];"
                 : "=r"(r[0]), "=r"(r[1]), "=r"(r[2]), "=r"(r[3]) : "r"(addr));
}

static __device__ __forceinline__ void mma_16816(float* c, const uint32_t* a, const uint32_t* b) {
    asm volatile(
        "mma.sync.aligned.m16n8k16.row.col.f32.f16.f16.f32 "
        "{%0,%1,%2,%3}, {%4,%5,%6,%7}, {%8,%9}, {%0,%1,%2,%3};"
        : "+f"(c[0]), "+f"(c[1]), "+f"(c[2]), "+f"(c[3])
        : "r"(a[0]), "r"(a[1]), "r"(a[2]), "r"(a[3]), "r"(b[0]), "r"(b[1]));
}

// ---------------- Kernel 1: mix expert weights -> fp16 ----------------
// grid (256, 4): blockIdx.y owns 8 groups.
__global__ void mix_weights_kernel(const float* __restrict__ coeff,
                                   const float* __restrict__ we,
                                   const float* __restrict__ ws)
{
    __shared__ float c_sm[NGRP * NEXP];
    int t = threadIdx.x;
    c_sm[t] = coeff[t];
    __syncthreads();

    int p = blockIdx.x * 256 + t;            // float4 index 0..65535
    const float4* ws4 = reinterpret_cast<const float4*>(ws);
    const float4* we4 = reinterpret_cast<const float4*>(we);
    float4 s = ws4[p];
    float4 e4[NEXP];
#pragma unroll
    for (int e = 0; e < NEXP; e++) e4[e] = we4[e * 65536 + p];

    const int g0 = blockIdx.y * 8;
#pragma unroll
    for (int gi = 0; gi < 8; gi++) {
        const int g = g0 + gi;
        const float* cg = c_sm + g * NEXP;
        float4 acc = s;
#pragma unroll
        for (int e = 0; e < NEXP; e++) {
            acc.x = fmaf(cg[e], e4[e].x, acc.x);
            acc.y = fmaf(cg[e], e4[e].y, acc.y);
            acc.z = fmaf(cg[e], e4[e].z, acc.z);
            acc.w = fmaf(cg[e], e4[e].w, acc.w);
        }
        __half2 p01 = __floats2half2_rn(acc.x, acc.y);
        __half2 p23 = __floats2half2_rn(acc.z, acc.w);
        uint2 packed = make_uint2(*reinterpret_cast<uint32_t*>(&p01),
                                  *reinterpret_cast<uint32_t*>(&p23));
        reinterpret_cast<uint2*>(g_w)[(size_t)g * 65536 + p] = packed;
    }
}

// ---------------- Kernel 2: mix bias ----------------
__global__ void mix_bias_kernel(const float* __restrict__ coeff,
                                const float* __restrict__ be,
                                const float* __restrict__ bs)
{
    int g = blockIdx.x;
    int n = threadIdx.x;
    float acc = bs[n];
#pragma unroll
    for (int e = 0; e < NEXP; e++)
        acc = fmaf(coeff[g * NEXP + e], be[e * OUT_F + n], acc);
    g_bias_mix[g * OUT_F + n] = acc;
}

// ---------------- Kernel 3: grouped GEMM with fused A fp32->fp16 ----------------
// CTA 128x128, 8 warps (warp 32x64), occ=2. K = 16 chunks of 32.
// A: LDG fp32 (prefetched 2 chunks ahead, 16 floats/thread) -> cvt fp16 -> STS,
//    double-buffered. x fp32 re-read per nt, but the 4 sharers are adjacent
//    blockIdx -> co-resident -> L2 hits. No conversion pre-pass.
// W: 3-buffer cp.async ring, wait_group 1 (one chunk of slack).
// One __syncthreads per chunk. 80B rows -> conflict-free ldmatrix phases.
#define ROWB    80
#define TILE    (128 * ROWB)             // 10240 B
#define AOFF(b)   ((b) * TILE)           // 2 A buffers
#define WOFF(s)   ((2 + (s)) * TILE)     // 3 W buffers
#define SMEM_TOTAL (5 * TILE)            // 51200 B -> 2 CTAs/SM

__global__ void __launch_bounds__(256, 2)
moe_gemm_kernel(const float* __restrict__ x, float* __restrict__ out)
{
    extern __shared__ __align__(128) uint8_t smem[];
    const uint32_t sb = smem_u32(smem);

    const int tid  = threadIdx.x;
    const int lane = tid & 31;
    const int wid  = tid >> 5;
    const int wm   = (wid & 3) * 32;   // warp m offset
    const int wn   = (wid >> 2) * 64;  // warp n offset

    const int bx = blockIdx.x;          // 0..2047
    const int g  = bx >> 6;
    const int mt = (bx >> 2) & 15;
    const int nt = bx & 3;
    const int m0 = g * TPG + mt * 128;
    const int n0 = nt * 128;

    const __half* wg = g_w + (size_t)g * OUT_F * IN_F + (size_t)n0 * IN_F;

    // A roles: 2 threads per row, 16 floats each
    const int arow  = tid >> 1;
    const int ahalf = tid & 1;
    const float* asrc = x + (size_t)(m0 + arow) * IN_F + ahalf * 16;
    const uint32_t aoff = (uint32_t)(arow * ROWB + ahalf * 32);

    float4 v0, v1, v2, v3;    // A staging (one chunk)

    auto ldgA = [&](int kc) {
        const float4* s = reinterpret_cast<const float4*>(asrc + kc * CHUNK);
        v0 = s[0]; v1 = s[1]; v2 = s[2]; v3 = s[3];
    };
    auto stsA = [&](int b) {
        __half2 h0 = __floats2half2_rn(v0.x, v0.y);
        __half2 h1 = __floats2half2_rn(v0.z, v0.w);
        __half2 h2 = __floats2half2_rn(v1.x, v1.y);
        __half2 h3 = __floats2half2_rn(v1.z, v1.w);
        __half2 h4 = __floats2half2_rn(v2.x, v2.y);
        __half2 h5 = __floats2half2_rn(v2.z, v2.w);
        __half2 h6 = __floats2half2_rn(v3.x, v3.y);
        __half2 h7 = __floats2half2_rn(v3.z, v3.w);
        uint8_t* dst = smem + AOFF(b) + aoff;
        *reinterpret_cast<uint4*>(dst) =
            make_uint4(*reinterpret_cast<uint32_t*>(&h0), *reinterpret_cast<uint32_t*>(&h1),
                       *reinterpret_cast<uint32_t*>(&h2), *reinterpret_cast<uint32_t*>(&h3));
        *reinterpret_cast<uint4*>(dst + 16) =
            make_uint4(*reinterpret_cast<uint32_t*>(&h4), *reinterpret_cast<uint32_t*>(&h5),
                       *reinterpret_cast<uint32_t*>(&h6), *reinterpret_cast<uint32_t*>(&h7));
    };
    auto cpW = [&](int kc, int s) {
#pragma unroll
        for (int u = 0; u < 2; u++) {
            const int lin = tid + u * 256;      // 0..511
            const int row = lin >> 2;           // 0..127
            const int seg = lin & 3;            // 16B segment
            cp_async16_cg(sb + WOFF(s) + row * ROWB + seg * 16,
                          wg + (size_t)row * IN_F + kc * CHUNK + seg * 8);
        }
        cp_async_commit();
    };

    float acc[2][8][4];
#pragma unroll
    for (int i = 0; i < 2; i++)
#pragma unroll
        for (int j = 0; j < 8; j++)
#pragma unroll
            for (int kk = 0; kk < 4; kk++) acc[i][j][kk] = 0.0f;

    // ---- prologue ----
    cpW(0, 0);
    cpW(1, 1);
    ldgA(0);
    stsA(0);
    ldgA(1);

    // ---- mainloop: 16 chunks, one barrier per chunk ----
    for (int kc = 0; kc < 16; kc++) {
        const int wbuf = kc % 3;
        const int abuf = kc & 1;

        if (kc < 15) asm volatile("cp.async.wait_group 1;" ::: "memory");
        else         asm volatile("cp.async.wait_group 0;" ::: "memory");
        __syncthreads();

        // store A(kc+1) into the buffer whose readers finished last iter;
        // prefetch chunk kc+2 (full iteration of latency slack)
        if (kc + 1 < 16) stsA(abuf ^ 1);
        if (kc + 2 < 16) {
            ldgA(kc + 2);
            cpW(kc + 2, (kc + 2) % 3);
        }

        const uint32_t a_b = sb + AOFF(abuf);
        const uint32_t w_b = sb + WOFF(wbuf);

#pragma unroll
        for (int s = 0; s < 2; s++) {
            uint32_t bfr[16];
#pragma unroll
            for (int p = 0; p < 4; p++) {
                const uint32_t baddr = w_b
                    + (uint32_t)(wn + p * 16 + (lane >> 4) * 8 + (lane & 7)) * ROWB
                    + s * 32 + ((lane >> 3) & 1) * 16;
                ldm_x4(bfr + p * 4, baddr);
            }
            uint32_t ah[2][4];
#pragma unroll
            for (int m = 0; m < 2; m++) {
                const uint32_t aaddr = a_b
                    + (uint32_t)(wm + m * 16 + (lane & 15)) * ROWB
                    + s * 32 + (lane >> 4) * 16;
                ldm_x4(ah[m], aaddr);
            }
#pragma unroll
            for (int m = 0; m < 2; m++) {
#pragma unroll
                for (int n = 0; n < 8; n++) {
                    const uint32_t* bp = bfr + (n >> 1) * 4 + (n & 1) * 2;
                    mma_16816(acc[m][n], ah[m], bp);
                }
            }
        }
    }

    // ---- epilogue: bias add + direct float2 stores ----
    const float* bias = g_bias_mix + g * OUT_F + n0;
    const int crow = lane >> 2;
    const int ccol2 = 2 * (lane & 3);
#pragma unroll
    for (int m = 0; m < 2; m++) {
        const int row = m0 + wm + m * 16 + crow;
#pragma unroll
        for (int n = 0; n < 8; n++) {
            const int col = wn + n * 8 + ccol2;
            const float2 bv = *reinterpret_cast<const float2*>(bias + col);
            float2 o0 = make_float2(acc[m][n][0] + bv.x, acc[m][n][1] + bv.y);
            float2 o1 = make_float2(acc[m][n][2] + bv.x, acc[m][n][3] + bv.y);
            *reinterpret_cast<float2*>(out + (size_t)row * OUT_F + n0 + col) = o0;
            *reinterpret_cast<float2*>(out + (size_t)(row + 8) * OUT_F + n0 + col) = o1;
        }
    }
}

// ---------------- Launch ----------------
extern "C" void kernel_launch(void* const* d_in, const int* in_sizes, int n_in,
                              void* d_out, int out_size)
{
    const float* x     = (const float*)d_in[0];
    const float* coeff = (const float*)d_in[1];
    const float* we    = (const float*)d_in[2];
    const float* be    = (const float*)d_in[3];
    const float* ws    = (const float*)d_in[4];
    const float* bs    = (const float*)d_in[5];
    float* out = (float*)d_out;

    cudaFuncSetAttribute(moe_gemm_kernel,
                         cudaFuncAttributeMaxDynamicSharedMemorySize, SMEM_TOTAL);

    mix_weights_kernel<<<dim3(256, 4), 256>>>(coeff, we, ws);
    mix_bias_kernel<<<NGRP, OUT_F>>>(coeff, be, bs);
    moe_gemm_kernel<<<NGRP * 16 * 4, 256, SMEM_TOTAL>>>(x, out);
}